// round 15
// baseline (speedup 1.0000x reference)
#include <cuda_runtime.h>
#include <cuda_fp16.h>
#include <math.h>
#include <stdint.h>

// Problem constants
#define BATCH 8
#define NPTS 256
#define HD 128
#define BN (BATCH*NPTS)          // 2048 rows
#define BSTRIDE 136              // padded row stride (fp16 elems) for ldmatrix
#define ROWB (BSTRIDE*2)         // 272 bytes per row
#define JT 32                    // j-tile rows
#define BT_HALF (128*ROWB)       // 34816 : B tile (fp16)
#define ABUF_BYTES (JT*ROWB)     // 8704 per A buffer (single fp16 tile)

// ---------------- scratch (device globals; no allocation allowed) ----------
__device__ float g_PA[BN*HD];
__device__ float g_PB[BN*HD];
__device__ float g_CA[BN*HD];
__device__ float g_CB[BN*HD];
__device__ float g_D2[BN*NPTS];
__device__ float g_D02[BN*NPTS];
__device__ float g_agg[BN*HD];
__device__ float g_upd[BN*3];
// W2^T in padded [n][k] fp16 layout (prep_kernel fills)
__device__ __align__(16) __half g_eBh[128*BSTRIDE];
__device__ __align__(16) __half g_cBh[128*BSTRIDE];

// precise sigmoid (gates only)
__device__ __forceinline__ float sigm(float v) {
    return __fdividef(1.f, 1.f + __expf(-v));
}
__device__ __forceinline__ float siluf(float v) {
    return v * sigm(v);
}
// fast silu: 1 MUFU (tanh.approx); R10 measured: no rel_err impact.
__device__ __forceinline__ float silu_fast(float v) {
    float h = 0.5f * v;
    float t;
    asm("tanh.approx.f32 %0, %1;" : "=f"(t) : "f"(h));
    return fmaf(h, t, h);
}

__device__ __forceinline__ uint32_t smem_u32(const void* p) {
    uint32_t a;
    asm("{ .reg .u64 tmp; cvta.to.shared.u64 tmp, %1; cvt.u32.u64 %0, tmp; }"
        : "=r"(a) : "l"(p));
    return a;
}

__device__ __forceinline__ void ldsm4(uint32_t r[4], uint32_t addr) {
    asm volatile("ldmatrix.sync.aligned.m8n8.x4.shared.b16 {%0,%1,%2,%3}, [%4];"
        : "=r"(r[0]), "=r"(r[1]), "=r"(r[2]), "=r"(r[3]) : "r"(addr));
}

__device__ __forceinline__ void mma_f16(float d[4], const uint32_t a[4],
                                        const uint32_t b0, const uint32_t b1) {
    asm volatile(
        "mma.sync.aligned.m16n8k16.row.col.f32.f16.f16.f32 "
        "{%0,%1,%2,%3}, {%4,%5,%6,%7}, {%8,%9}, {%0,%1,%2,%3};"
        : "+f"(d[0]), "+f"(d[1]), "+f"(d[2]), "+f"(d[3])
        : "r"(a[0]), "r"(a[1]), "r"(a[2]), "r"(a[3]), "r"(b0), "r"(b1));
}

// ---------------- kernel 0: prep W2^T fp16 padded tiles --------------------
__global__ void __launch_bounds__(128) prep_kernel(
    const float* __restrict__ e2w, const float* __restrict__ c2w)
{
    int n = blockIdx.x;
    int k = threadIdx.x;
    int idx = n * BSTRIDE + k;
    g_eBh[idx] = __float2half_rn(e2w[k * HD + n]);
    g_cBh[idx] = __float2half_rn(c2w[k * HD + n]);
}

// ---------------- kernel 1: per-node projections ---------------------------
__global__ void __launch_bounds__(128) proj_kernel(
    const float* __restrict__ h,
    const float* __restrict__ e1w,
    const float* __restrict__ c1w)
{
    const int r0 = blockIdx.x * 8;
    const int t  = threadIdx.x;
    __shared__ float hs[8][HD];
    #pragma unroll
    for (int r = 0; r < 8; r++) hs[r][t] = h[(r0 + r) * HD + t];
    __syncthreads();

    float pa[8], pb[8], ca[8], cb[8];
    #pragma unroll
    for (int r = 0; r < 8; r++) { pa[r]=0.f; pb[r]=0.f; ca[r]=0.f; cb[r]=0.f; }

    for (int k = 0; k < HD; k++) {
        float wea = e1w[k * HD + t];
        float web = e1w[(HD + k) * HD + t];
        float wca = c1w[k * HD + t];
        float wcb = c1w[(HD + k) * HD + t];
        #pragma unroll
        for (int r = 0; r < 8; r++) {
            float hk = hs[r][k];
            pa[r] = fmaf(hk, wea, pa[r]);
            pb[r] = fmaf(hk, web, pb[r]);
            ca[r] = fmaf(hk, wca, ca[r]);
            cb[r] = fmaf(hk, wcb, cb[r]);
        }
    }
    #pragma unroll
    for (int r = 0; r < 8; r++) {
        int bi = r0 + r;
        g_PA[bi * HD + t] = pa[r];
        g_PB[bi * HD + t] = pb[r];
        g_CA[bi * HD + t] = ca[r];
        g_CB[bi * HD + t] = cb[r];
    }
}

// ---------------- kernel 2: pairwise squared distances ---------------------
__global__ void __launch_bounds__(256) dist_kernel(
    const float* __restrict__ x, const float* __restrict__ x0)
{
    int idx = blockIdx.x * 256 + threadIdx.x;
    int j = idx & 255;
    int bi = idx >> 8;
    int b  = bi >> 8;
    const float* xi = x  + bi * 3;
    const float* xj = x  + (b * NPTS + j) * 3;
    float dx = xi[0]-xj[0], dy = xi[1]-xj[1], dz = xi[2]-xj[2];
    g_D2[idx] = dx*dx + dy*dy + dz*dz;
    const float* yi = x0 + bi * 3;
    const float* yj = x0 + (b * NPTS + j) * 3;
    float ex = yi[0]-yj[0], ey = yi[1]-yj[1], ez = yi[2]-yj[2];
    g_D02[idx] = ex*ex + ey*ey + ez*ez;
}

// ============================================================================
// smem layout (bytes):
//   [0      : 8704)    A buffer 0 (32 x 136 fp16)
//   [8704   : 17408)   A buffer 1
//   [17408  : 52224)   B tile (128 x 136 fp16)  -- read once into registers
//   [52224  : ...)     ext float scratch
// ============================================================================
#define OFF_BH   17408
#define OFF_EXT  52224
#define E_SMEM_TOTAL (OFF_EXT + 1184*4)
#define C_SMEM_TOTAL (OFF_EXT + 992*4)

// producer: single row rr of the warp's 4-row slice; lane -> k=lane*4..+3.
__device__ __forceinline__ void produce_row(
    int w, int lane, int j0, int rr,
    const float4 pab, const float4 w256_4, const float4 w257_4,
    const float* __restrict__ Pbase,
    const float* d2all, const float* d02all,
    uint32_t aBuf)
{
    const int k0 = lane * 4;
    int row = w * 4 + rr;
    const float4 pb4 = *reinterpret_cast<const float4*>(
        &Pbase[(size_t)(j0 + row) * HD + k0]);
    float dj = d2all[j0 + row], d0j = d02all[j0 + row];
    float v0 = silu_fast(pab.x + pb4.x + dj * w256_4.x + d0j * w257_4.x);
    float v1 = silu_fast(pab.y + pb4.y + dj * w256_4.y + d0j * w257_4.y);
    float v2 = silu_fast(pab.z + pb4.z + dj * w256_4.z + d0j * w257_4.z);
    float v3 = silu_fast(pab.w + pb4.w + dj * w256_4.w + d0j * w257_4.w);
    __half2 H01 = __floats2half2_rn(v0, v1);
    __half2 H23 = __floats2half2_rn(v2, v3);
    uint32_t off = row * ROWB + lane * 8;
    asm volatile("st.shared.v2.b32 [%0], {%1, %2};"
        :: "r"(aBuf + off),
           "r"(*reinterpret_cast<uint32_t*>(&H01)),
           "r"(*reinterpret_cast<uint32_t*>(&H23)) : "memory");
}

// load this warp's B fragments for all 8 k-steps into registers (64 regs)
__device__ __forceinline__ void load_B_frags(
    uint32_t bfr[8][8], int ncol0, int lane, uint32_t bH32)
{
    uint32_t boff[2];
    int bn = (lane & 7) + ((lane >> 4) & 1) * 8;
    int bkp = ((lane >> 3) & 1) * 8;
    #pragma unroll
    for (int nb = 0; nb < 2; nb++)
        boff[nb] = (ncol0 + nb * 16 + bn) * ROWB + bkp * 2;
    #pragma unroll
    for (int ks = 0; ks < 8; ks++) {
        ldsm4(&bfr[ks][0], bH32 + boff[0] + ks * 32);
        ldsm4(&bfr[ks][4], bH32 + boff[1] + ks * 32);
    }
}

// ---------------- kernel 3: edge chain -> g_agg ----------------------------
// ext floats: d2all[256] d02all[256] b2s[128] eiws[128] dotP[128] e_s[32] aggW[256]
__global__ void __launch_bounds__(256, 2) edge_kernel(
    const float* __restrict__ e1w, const float* __restrict__ e1b,
    const float* __restrict__ e2b,
    const float* __restrict__ eiw, const float* __restrict__ eib)
{
    extern __shared__ __align__(16) unsigned char smem[];
    float* ext    = (float*)(smem + OFF_EXT);
    float* d2all  = ext;         float* d02all = ext + 256;
    float* b2s    = ext + 512;   float* eiws   = ext + 640;
    float* dotP   = ext + 768;   // 4*32
    float* e_s    = ext + 896;   // 32
    float* aggW   = ext + 928;   // 8*32

    const uint32_t smem32 = smem_u32(smem);
    const uint32_t bH32 = smem32 + OFF_BH;

    const int bi = blockIdx.x;
    const int b  = bi >> 8;
    const int i  = bi & 255;
    const int t  = threadIdx.x;
    const int lane = t & 31, w = t >> 5;
    const int s = lane & 3, q = lane >> 2;
    const int mrow0 = (w & 1) * 16, ncol0 = (w >> 1) * 32;

    {
        const uint4* srcH = (const uint4*)g_eBh;
        uint4* dstH = (uint4*)(smem + OFF_BH);
        for (int idx = t; idx < BT_HALF/16; idx += 256)
            dstH[idx] = srcH[idx];
    }
    if (t < 128) { b2s[t] = e2b[t]; eiws[t] = eiw[t]; }
    d2all[t]  = g_D2 [bi * NPTS + t];
    d02all[t] = g_D02[bi * NPTS + t];

    const int k0 = lane * 4;
    float4 pab = *reinterpret_cast<const float4*>(&g_PA[bi * HD + k0]);
    const float4 b1_4 = *reinterpret_cast<const float4*>(&e1b[k0]);
    pab.x += b1_4.x; pab.y += b1_4.y; pab.z += b1_4.z; pab.w += b1_4.w;
    const float4 w256_4 = *reinterpret_cast<const float4*>(&e1w[256 * HD + k0]);
    const float4 w257_4 = *reinterpret_cast<const float4*>(&e1w[257 * HD + k0]);
    const float bi0 = eib[0];
    const float* PBb = g_PB + (size_t)b * NPTS * HD;

    float aggacc[8];
    #pragma unroll
    for (int c = 0; c < 8; c++) aggacc[c] = 0.f;

    __syncthreads();
    // B fragments: load once into registers (B smem never read again)
    uint32_t bfr[8][8];
    load_B_frags(bfr, ncol0, lane, bH32);
    #pragma unroll
    for (int rr = 0; rr < 4; rr++)
        produce_row(w, lane, 0, rr, pab, w256_4, w257_4, PBb,
                    d2all, d02all, smem32);
    __syncthreads();

    const uint32_t aoff = (mrow0 + (lane & 15)) * ROWB + (lane >> 4) * 16;

    for (int tile = 0; tile < 8; tile++) {
        const int j0 = tile * JT;
        const uint32_t aBuf  = smem32 + (tile & 1) * ABUF_BYTES;
        const uint32_t aNext = smem32 + ((tile + 1) & 1) * ABUF_BYTES;
        const bool doProd = (tile < 7);

        float acc[4][4];
        #pragma unroll
        for (int a = 0; a < 4; a++)
            #pragma unroll
            for (int e = 0; e < 4; e++) acc[a][e] = 0.f;

        // interleaved GEMM + producer: one producer row between k-steps 0-3
        #pragma unroll
        for (int ks = 0; ks < 8; ks++) {
            uint32_t ah[4];
            ldsm4(ah, aBuf + aoff + ks * 32);
            mma_f16(acc[0], ah, bfr[ks][0], bfr[ks][1]);
            mma_f16(acc[1], ah, bfr[ks][2], bfr[ks][3]);
            if (ks < 4 && doProd)
                produce_row(w, lane, j0 + JT, ks, pab, w256_4, w257_4,
                            PBb, d2all, d02all, aNext);
            mma_f16(acc[2], ah, bfr[ks][4], bfr[ks][5]);
            mma_f16(acc[3], ah, bfr[ks][6], bfr[ks][7]);
        }

        // m = silu(D + b2); per-row dots with eiw
        float dot0 = 0.f, dot1 = 0.f;
        #pragma unroll
        for (int ni = 0; ni < 4; ni++) {
            int c0 = ncol0 + ni * 8 + 2 * s;
            float b2a = b2s[c0], b2b = b2s[c0 + 1];
            float* A = acc[ni];
            A[0] = silu_fast(A[0] + b2a); A[1] = silu_fast(A[1] + b2b);
            A[2] = silu_fast(A[2] + b2a); A[3] = silu_fast(A[3] + b2b);
            float ea = eiws[c0], eb = eiws[c0 + 1];
            dot0 += A[0]*ea + A[1]*eb;
            dot1 += A[2]*ea + A[3]*eb;
        }
        dot0 += __shfl_xor_sync(0xffffffffu, dot0, 1);
        dot0 += __shfl_xor_sync(0xffffffffu, dot0, 2);
        dot1 += __shfl_xor_sync(0xffffffffu, dot1, 1);
        dot1 += __shfl_xor_sync(0xffffffffu, dot1, 2);
        if (s == 0) {
            dotP[(w >> 1) * JT + mrow0 + q]     = dot0;
            dotP[(w >> 1) * JT + mrow0 + q + 8] = dot1;
        }
        __syncthreads();
        if (t < JT) {
            float sv = dotP[t] + dotP[JT + t] + dotP[2*JT + t]
                     + dotP[3*JT + t] + bi0;
            float e = sigm(sv);
            if (j0 + t == i) e = 0.f;
            e_s[t] = e;
        }
        __syncthreads();
        {
            float e0 = e_s[mrow0 + q], e1 = e_s[mrow0 + q + 8];
            #pragma unroll
            for (int ni = 0; ni < 4; ni++) {
                float* A = acc[ni];
                aggacc[ni*2+0] = fmaf(e0, A[0], fmaf(e1, A[2], aggacc[ni*2+0]));
                aggacc[ni*2+1] = fmaf(e0, A[1], fmaf(e1, A[3], aggacc[ni*2+1]));
            }
        }
        // no end barrier needed: next iter's dotP write is preceded by this
        // iter's sync #2, and buffer hazards are separated by >= one barrier.
    }
    // reduce aggacc over q-lanes (cols depend only on s)
    #pragma unroll
    for (int c = 0; c < 8; c++) {
        float v = aggacc[c];
        v += __shfl_xor_sync(0xffffffffu, v, 4);
        v += __shfl_xor_sync(0xffffffffu, v, 8);
        v += __shfl_xor_sync(0xffffffffu, v, 16);
        aggacc[c] = v;
    }
    __syncthreads();
    if (q == 0) {
        #pragma unroll
        for (int ni = 0; ni < 4; ni++) {
            aggW[w * 32 + ni * 8 + 2 * s]     = aggacc[ni*2+0];
            aggW[w * 32 + ni * 8 + 2 * s + 1] = aggacc[ni*2+1];
        }
    }
    __syncthreads();
    if (t < 128) {
        int cq = t >> 5, cl = t & 31;
        float sv = aggW[(2*cq) * 32 + cl] + aggW[(2*cq + 1) * 32 + cl];
        g_agg[bi * HD + t] = sv * (1.0f / 256.0f);
    }
}

// ---------------- kernel 4: coordinate chain -> g_upd ----------------------
// ext floats: d2all[256] d02all[256] b2s[128] c3ws[128] dotP[128] updx/y/z[32]
__global__ void __launch_bounds__(256, 2) cor_kernel(
    const float* __restrict__ c1w, const float* __restrict__ c1b,
    const float* __restrict__ c2b,
    const float* __restrict__ c3w, const float* __restrict__ c3b,
    const float* __restrict__ x)
{
    extern __shared__ __align__(16) unsigned char smem[];
    float* ext    = (float*)(smem + OFF_EXT);
    float* d2all  = ext;         float* d02all = ext + 256;
    float* b2s    = ext + 512;   float* c3ws   = ext + 640;
    float* dotP   = ext + 768;   // 4*32
    float* updx   = ext + 896;   float* updy = ext + 928;  float* updz = ext + 960;

    const uint32_t smem32 = smem_u32(smem);
    const uint32_t bH32 = smem32 + OFF_BH;

    const int bi = blockIdx.x;
    const int b  = bi >> 8;
    const int i  = bi & 255;
    const int t  = threadIdx.x;
    const int lane = t & 31, w = t >> 5;
    const int s = lane & 3, q = lane >> 2;
    const int mrow0 = (w & 1) * 16, ncol0 = (w >> 1) * 32;

    {
        const uint4* srcH = (const uint4*)g_cBh;
        uint4* dstH = (uint4*)(smem + OFF_BH);
        for (int idx = t; idx < BT_HALF/16; idx += 256)
            dstH[idx] = srcH[idx];
    }
    if (t < 128) { b2s[t] = c2b[t]; c3ws[t] = c3w[t]; }
    d2all[t]  = g_D2 [bi * NPTS + t];
    d02all[t] = g_D02[bi * NPTS + t];

    const int k0 = lane * 4;
    float4 pab = *reinterpret_cast<const float4*>(&g_CA[bi * HD + k0]);
    const float4 b1_4 = *reinterpret_cast<const float4*>(&c1b[k0]);
    pab.x += b1_4.x; pab.y += b1_4.y; pab.z += b1_4.z; pab.w += b1_4.w;
    const float4 w256_4 = *reinterpret_cast<const float4*>(&c1w[256 * HD + k0]);
    const float4 w257_4 = *reinterpret_cast<const float4*>(&c1w[257 * HD + k0]);
    const float b3 = c3b[0];
    const float* CBb = g_CB + (size_t)b * NPTS * HD;

    const float xi0 = x[bi * 3 + 0];
    const float xi1 = x[bi * 3 + 1];
    const float xi2 = x[bi * 3 + 2];
    float ux = 0.f, uy = 0.f, uz = 0.f;

    __syncthreads();
    uint32_t bfr[8][8];
    load_B_frags(bfr, ncol0, lane, bH32);
    #pragma unroll
    for (int rr = 0; rr < 4; rr++)
        produce_row(w, lane, 0, rr, pab, w256_4, w257_4, CBb,
                    d2all, d02all, smem32);
    __syncthreads();

    const uint32_t aoff = (mrow0 + (lane & 15)) * ROWB + (lane >> 4) * 16;

    for (int tile = 0; tile < 8; tile++) {
        const int j0 = tile * JT;
        const uint32_t aBuf  = smem32 + (tile & 1) * ABUF_BYTES;
        const uint32_t aNext = smem32 + ((tile + 1) & 1) * ABUF_BYTES;
        const bool doProd = (tile < 7);

        float acc[4][4];
        #pragma unroll
        for (int a = 0; a < 4; a++)
            #pragma unroll
            for (int e = 0; e < 4; e++) acc[a][e] = 0.f;

        #pragma unroll
        for (int ks = 0; ks < 8; ks++) {
            uint32_t ah[4];
            ldsm4(ah, aBuf + aoff + ks * 32);
            mma_f16(acc[0], ah, bfr[ks][0], bfr[ks][1]);
            mma_f16(acc[1], ah, bfr[ks][2], bfr[ks][3]);
            if (ks < 4 && doProd)
                produce_row(w, lane, j0 + JT, ks, pab, w256_4, w257_4,
                            CBb, d2all, d02all, aNext);
            mma_f16(acc[2], ah, bfr[ks][4], bfr[ks][5]);
            mma_f16(acc[3], ah, bfr[ks][6], bfr[ks][7]);
        }

        float dot0 = 0.f, dot1 = 0.f;
        #pragma unroll
        for (int ni = 0; ni < 4; ni++) {
            int c0 = ncol0 + ni * 8 + 2 * s;
            float b2a = b2s[c0], b2b = b2s[c0 + 1];
            float* A = acc[ni];
            float m0 = silu_fast(A[0] + b2a), m1 = silu_fast(A[1] + b2b);
            float m2 = silu_fast(A[2] + b2a), m3 = silu_fast(A[3] + b2b);
            float wa = c3ws[c0], wb = c3ws[c0 + 1];
            dot0 += m0*wa + m1*wb;
            dot1 += m2*wa + m3*wb;
        }
        dot0 += __shfl_xor_sync(0xffffffffu, dot0, 1);
        dot0 += __shfl_xor_sync(0xffffffffu, dot0, 2);
        dot1 += __shfl_xor_sync(0xffffffffu, dot1, 1);
        dot1 += __shfl_xor_sync(0xffffffffu, dot1, 2);
        if (s == 0) {
            dotP[(w >> 1) * JT + mrow0 + q]     = dot0;
            dotP[(w >> 1) * JT + mrow0 + q + 8] = dot1;
        }
        __syncthreads();
        if (t < JT) {
            int j = j0 + t;
            if (j != i) {
                float cw = dotP[t] + dotP[JT + t] + dotP[2*JT + t]
                         + dotP[3*JT + t] + b3;
                float d2v = d2all[j];
                float dist = (d2v > 0.f) ? sqrtf(d2v) : 0.f;
                float f = __fdividef(cw, dist + 1.f);
                const float* xj = x + ((size_t)b * NPTS + j) * 3;
                ux = fmaf(f, xi0 - xj[0], ux);
                uy = fmaf(f, xi1 - xj[1], uy);
                uz = fmaf(f, xi2 - xj[2], uz);
            }
        }
        __syncthreads();   // protect dotP from next iter's writes
    }
    if (t < JT) { updx[t] = ux; updy[t] = uy; updz[t] = uz; }
    __syncthreads();
    if (t < 3) {
        const float* arr = (t == 0) ? updx : (t == 1) ? updy : updz;
        float sv = 0.f;
        for (int r = 0; r < JT; r++) sv += arr[r];
        g_upd[bi * 3 + t] = sv * (1.0f / 256.0f);
    }
}

// ---------------- kernel 5: node MLP + outputs -----------------------------
__global__ void __launch_bounds__(128) final_kernel(
    const float* __restrict__ hin, const float* __restrict__ xin,
    const float* __restrict__ pm,
    const float* __restrict__ n1w, const float* __restrict__ n1b,
    const float* __restrict__ n2w, const float* __restrict__ n2b,
    float* __restrict__ out)
{
    const int r0 = blockIdx.x * 8;
    const int t  = threadIdx.x;
    __shared__ float nin[8][256];
    __shared__ float tmid[8][HD];
    #pragma unroll
    for (int r = 0; r < 8; r++) {
        nin[r][t]       = hin[(r0 + r) * HD + t];
        nin[r][HD + t]  = g_agg[(r0 + r) * HD + t];
    }
    __syncthreads();
    float a[8];
    #pragma unroll
    for (int r = 0; r < 8; r++) a[r] = n1b[t];
    for (int k = 0; k < 256; k++) {
        float wv = n1w[k * HD + t];
        #pragma unroll
        for (int r = 0; r < 8; r++) a[r] = fmaf(nin[r][k], wv, a[r]);
    }
    #pragma unroll
    for (int r = 0; r < 8; r++) tmid[r][t] = siluf(a[r]);
    __syncthreads();
    #pragma unroll
    for (int r = 0; r < 8; r++) a[r] = n2b[t];
    for (int k = 0; k < HD; k++) {
        float wv = n2w[k * HD + t];
        #pragma unroll
        for (int r = 0; r < 8; r++) a[r] = fmaf(tmid[r][k], wv, a[r]);
    }
    float* outx = out;                  // x_next: BN*3
    float* outh = out + BN * 3;         // h_next: BN*HD
    #pragma unroll
    for (int r = 0; r < 8; r++) {
        int bi = r0 + r;
        float mask = pm[bi];
        outh[bi * HD + t] = (nin[r][t] + a[r]) * mask;
        if (t < 3) outx[bi * 3 + t] = (xin[bi * 3 + t] + g_upd[bi * 3 + t]) * mask;
    }
}

// ---------------- launch ----------------------------------------------------
extern "C" void kernel_launch(void* const* d_in, const int* in_sizes, int n_in,
                              void* d_out, int out_size)
{
    const float* x   = (const float*)d_in[0];
    const float* h   = (const float*)d_in[1];
    const float* x0  = (const float*)d_in[2];
    const float* pm  = (const float*)d_in[3];
    const float* e1w = (const float*)d_in[4];
    const float* e1b = (const float*)d_in[5];
    const float* e2w = (const float*)d_in[6];
    const float* e2b = (const float*)d_in[7];
    const float* eiw = (const float*)d_in[8];
    const float* eib = (const float*)d_in[9];
    const float* n1w = (const float*)d_in[10];
    const float* n1b = (const float*)d_in[11];
    const float* n2w = (const float*)d_in[12];
    const float* n2b = (const float*)d_in[13];
    const float* c1w = (const float*)d_in[14];
    const float* c1b = (const float*)d_in[15];
    const float* c2w = (const float*)d_in[16];
    const float* c2b = (const float*)d_in[17];
    const float* c3w = (const float*)d_in[18];
    const float* c3b = (const float*)d_in[19];
    float* out = (float*)d_out;

    cudaFuncSetAttribute(edge_kernel,
        cudaFuncAttributeMaxDynamicSharedMemorySize, E_SMEM_TOTAL);
    cudaFuncSetAttribute(cor_kernel,
        cudaFuncAttributeMaxDynamicSharedMemorySize, C_SMEM_TOTAL);

    prep_kernel<<<128, 128>>>(e2w, c2w);
    proj_kernel<<<BN / 8, 128>>>(h, e1w, c1w);
    dist_kernel<<<(BN * NPTS) / 256, 256>>>(x, x0);
    edge_kernel<<<BN, 256, E_SMEM_TOTAL>>>(e1w, e1b, e2b, eiw, eib);
    cor_kernel<<<BN, 256, C_SMEM_TOTAL>>>(c1w, c1b, c2b, c3w, c3b, x);
    final_kernel<<<BN / 8, 128>>>(h, x, pm, n1w, n1b, n2w, n2b, out);
}

// round 16
// speedup vs baseline: 1.2959x; 1.2959x over previous
#include <cuda_runtime.h>
#include <cuda_fp16.h>
#include <math.h>
#include <stdint.h>

// Problem constants
#define BATCH 8
#define NPTS 256
#define HD 128
#define BN (BATCH*NPTS)          // 2048 rows
#define BSTRIDE 136              // padded row stride (fp16 elems) for ldmatrix
#define ROWB (BSTRIDE*2)         // 272 bytes per row
#define JT 32                    // j-tile rows
#define BT_HALF (128*ROWB)       // 34816 : B tile (fp16)
#define ABUF_BYTES (JT*ROWB)     // 8704 per A buffer (single fp16 tile)

// ---------------- scratch (device globals; no allocation allowed) ----------
__device__ float g_PA[BN*HD];
__device__ float g_CA[BN*HD];
__device__ __align__(16) __half g_PBh[BN*HD];   // fp16 PB (producer operand)
__device__ __align__(16) __half g_CBh[BN*HD];   // fp16 CB
__device__ float g_D2[BN*NPTS];
__device__ float g_D02[BN*NPTS];
__device__ float g_agg[BN*HD];
__device__ float g_upd[BN*3];
// W2^T in padded [n][k] fp16 layout (prep_kernel fills)
__device__ __align__(16) __half g_eBh[128*BSTRIDE];
__device__ __align__(16) __half g_cBh[128*BSTRIDE];

// precise sigmoid (gates only)
__device__ __forceinline__ float sigm(float v) {
    return __fdividef(1.f, 1.f + __expf(-v));
}
__device__ __forceinline__ float siluf(float v) {
    return v * sigm(v);
}
// fast silu fp32: 1 MUFU (tanh.approx); R10 measured: no rel_err impact.
__device__ __forceinline__ float silu_fast(float v) {
    float h = 0.5f * v;
    float t;
    asm("tanh.approx.f32 %0, %1;" : "=f"(t) : "f"(h));
    return fmaf(h, t, h);
}
// packed half2 silu: 3 inst for 2 elements
__device__ __forceinline__ __half2 silu_h2(__half2 v) {
    __half2 h = __hmul2(v, __float2half2_rn(0.5f));
    uint32_t hu = *reinterpret_cast<uint32_t*>(&h);
    uint32_t tu;
    asm("tanh.approx.f16x2 %0, %1;" : "=r"(tu) : "r"(hu));
    __half2 t = *reinterpret_cast<__half2*>(&tu);
    return __hfma2(h, t, h);
}

__device__ __forceinline__ uint32_t smem_u32(const void* p) {
    uint32_t a;
    asm("{ .reg .u64 tmp; cvta.to.shared.u64 tmp, %1; cvt.u32.u64 %0, tmp; }"
        : "=r"(a) : "l"(p));
    return a;
}

__device__ __forceinline__ void ldsm4(uint32_t r[4], uint32_t addr) {
    asm volatile("ldmatrix.sync.aligned.m8n8.x4.shared.b16 {%0,%1,%2,%3}, [%4];"
        : "=r"(r[0]), "=r"(r[1]), "=r"(r[2]), "=r"(r[3]) : "r"(addr));
}

__device__ __forceinline__ void mma_f16(float d[4], const uint32_t a[4],
                                        const uint32_t b0, const uint32_t b1) {
    asm volatile(
        "mma.sync.aligned.m16n8k16.row.col.f32.f16.f16.f32 "
        "{%0,%1,%2,%3}, {%4,%5,%6,%7}, {%8,%9}, {%0,%1,%2,%3};"
        : "+f"(d[0]), "+f"(d[1]), "+f"(d[2]), "+f"(d[3])
        : "r"(a[0]), "r"(a[1]), "r"(a[2]), "r"(a[3]), "r"(b0), "r"(b1));
}

// ---------------- kernel 0: prep W2^T fp16 padded tiles --------------------
__global__ void __launch_bounds__(128) prep_kernel(
    const float* __restrict__ e2w, const float* __restrict__ c2w)
{
    int n = blockIdx.x;
    int k = threadIdx.x;
    int idx = n * BSTRIDE + k;
    g_eBh[idx] = __float2half_rn(e2w[k * HD + n]);
    g_cBh[idx] = __float2half_rn(c2w[k * HD + n]);
}

// ---------------- kernel 1: per-node projections ---------------------------
__global__ void __launch_bounds__(128) proj_kernel(
    const float* __restrict__ h,
    const float* __restrict__ e1w,
    const float* __restrict__ c1w)
{
    const int r0 = blockIdx.x * 8;
    const int t  = threadIdx.x;
    __shared__ float hs[8][HD];
    #pragma unroll
    for (int r = 0; r < 8; r++) hs[r][t] = h[(r0 + r) * HD + t];
    __syncthreads();

    float pa[8], pb[8], ca[8], cb[8];
    #pragma unroll
    for (int r = 0; r < 8; r++) { pa[r]=0.f; pb[r]=0.f; ca[r]=0.f; cb[r]=0.f; }

    for (int k = 0; k < HD; k++) {
        float wea = e1w[k * HD + t];
        float web = e1w[(HD + k) * HD + t];
        float wca = c1w[k * HD + t];
        float wcb = c1w[(HD + k) * HD + t];
        #pragma unroll
        for (int r = 0; r < 8; r++) {
            float hk = hs[r][k];
            pa[r] = fmaf(hk, wea, pa[r]);
            pb[r] = fmaf(hk, web, pb[r]);
            ca[r] = fmaf(hk, wca, ca[r]);
            cb[r] = fmaf(hk, wcb, cb[r]);
        }
    }
    #pragma unroll
    for (int r = 0; r < 8; r++) {
        int bi = r0 + r;
        g_PA[bi * HD + t]  = pa[r];
        g_CA[bi * HD + t]  = ca[r];
        g_PBh[bi * HD + t] = __float2half_rn(pb[r]);
        g_CBh[bi * HD + t] = __float2half_rn(cb[r]);
    }
}

// ---------------- kernel 2: pairwise squared distances ---------------------
__global__ void __launch_bounds__(256) dist_kernel(
    const float* __restrict__ x, const float* __restrict__ x0)
{
    int idx = blockIdx.x * 256 + threadIdx.x;
    int j = idx & 255;
    int bi = idx >> 8;
    int b  = bi >> 8;
    const float* xi = x  + bi * 3;
    const float* xj = x  + (b * NPTS + j) * 3;
    float dx = xi[0]-xj[0], dy = xi[1]-xj[1], dz = xi[2]-xj[2];
    g_D2[idx] = dx*dx + dy*dy + dz*dz;
    const float* yi = x0 + bi * 3;
    const float* yj = x0 + (b * NPTS + j) * 3;
    float ex = yi[0]-yj[0], ey = yi[1]-yj[1], ez = yi[2]-yj[2];
    g_D02[idx] = ex*ex + ey*ey + ez*ez;
}

// ============================================================================
// smem layout (bytes):
//   [0      : 8704)    A buffer 0 (32 x 136 fp16)
//   [8704   : 17408)   A buffer 1
//   [17408  : 52224)   B tile (128 x 136 fp16)
//   [52224  : ...)     ext scratch (32-bit words)
// ============================================================================
#define OFF_BH   17408
#define OFF_EXT  52224
#define E_SMEM_TOTAL (OFF_EXT + 1184*4)
#define C_SMEM_TOTAL (OFF_EXT + 1248*4)

// half2 producer: warp w -> local rows w*4..w*4+3; lane -> k = lane*4..+3.
// d2h/d02h: replicated half2 per j (uint32). Pbh: fp16 PB/CB.
__device__ __forceinline__ void produce_tile_h2(
    int w, int lane, int j0,
    __half2 pab01, __half2 pab23,
    __half2 w256_01, __half2 w256_23, __half2 w257_01, __half2 w257_23,
    const __half* __restrict__ Pbh,
    const uint32_t* d2h, const uint32_t* d02h,
    uint32_t aBuf)
{
    const int k0 = lane * 4;
    #pragma unroll
    for (int rr = 0; rr < 4; rr++) {
        int row = w * 4 + rr;
        const uint2 pb = *reinterpret_cast<const uint2*>(
            &Pbh[(size_t)(j0 + row) * HD + k0]);
        __half2 pb01 = *reinterpret_cast<const __half2*>(&pb.x);
        __half2 pb23 = *reinterpret_cast<const __half2*>(&pb.y);
        uint32_t dju = d2h[j0 + row], d0ju = d02h[j0 + row];
        __half2 dj  = *reinterpret_cast<__half2*>(&dju);
        __half2 d0j = *reinterpret_cast<__half2*>(&d0ju);
        __half2 v01 = __hadd2(pab01, pb01);
        v01 = __hfma2(dj, w256_01, v01);
        v01 = __hfma2(d0j, w257_01, v01);
        __half2 v23 = __hadd2(pab23, pb23);
        v23 = __hfma2(dj, w256_23, v23);
        v23 = __hfma2(d0j, w257_23, v23);
        v01 = silu_h2(v01);
        v23 = silu_h2(v23);
        uint32_t off = row * ROWB + lane * 8;
        asm volatile("st.shared.v2.b32 [%0], {%1, %2};"
            :: "r"(aBuf + off),
               "r"(*reinterpret_cast<uint32_t*>(&v01)),
               "r"(*reinterpret_cast<uint32_t*>(&v23)) : "memory");
    }
}

// warp GEMM: single-pass fp16; warp tile rows mrow0..+16, cols ncol0..+32.
__device__ __forceinline__ void gemm_warp(
    float acc[4][4], int mrow0, int ncol0, int lane,
    uint32_t aBuf, uint32_t bH32)
{
    uint32_t aoff, boff[2];
    {
        int arow = (lane & 15);
        int akp  = (lane >> 4) * 8;
        aoff = (mrow0 + arow) * ROWB + akp * 2;
        int bn = (lane & 7) + ((lane >> 4) & 1) * 8;
        int bkp = ((lane >> 3) & 1) * 8;
        #pragma unroll
        for (int nb = 0; nb < 2; nb++)
            boff[nb] = (ncol0 + nb * 16 + bn) * ROWB + bkp * 2;
    }
    #pragma unroll
    for (int ks = 0; ks < 8; ks++) {
        const uint32_t kb = ks * 32;
        uint32_t ah[4], bh[2][4];
        ldsm4(ah, aBuf + aoff + kb);
        #pragma unroll
        for (int nb = 0; nb < 2; nb++)
            ldsm4(bh[nb], bH32 + boff[nb] + kb);
        mma_f16(acc[0], ah, bh[0][0], bh[0][1]);
        mma_f16(acc[1], ah, bh[0][2], bh[0][3]);
        mma_f16(acc[2], ah, bh[1][0], bh[1][1]);
        mma_f16(acc[3], ah, bh[1][2], bh[1][3]);
    }
}

// ---------------- kernel 3: edge chain -> g_agg ----------------------------
// ext words: d2h[256] d02h[256] b2s[128] eiws[128] dotP[128] e_s[32] aggW[256]
__global__ void __launch_bounds__(256, 3) edge_kernel(
    const float* __restrict__ e1w, const float* __restrict__ e1b,
    const float* __restrict__ e2b,
    const float* __restrict__ eiw, const float* __restrict__ eib)
{
    extern __shared__ __align__(16) unsigned char smem[];
    uint32_t* extw = (uint32_t*)(smem + OFF_EXT);
    uint32_t* d2h   = extw;        uint32_t* d02h = extw + 256;
    float* ext    = (float*)(extw + 512);
    float* b2s    = ext;         float* eiws   = ext + 128;
    float* dotP   = ext + 256;   // 4*32
    float* e_s    = ext + 384;   // 32
    float* aggW   = ext + 416;   // 8*32

    const uint32_t smem32 = smem_u32(smem);
    const uint32_t bH32 = smem32 + OFF_BH;

    const int bi = blockIdx.x;
    const int b  = bi >> 8;
    const int i  = bi & 255;
    const int t  = threadIdx.x;
    const int lane = t & 31, w = t >> 5;
    const int s = lane & 3, q = lane >> 2;
    const int mrow0 = (w & 1) * 16, ncol0 = (w >> 1) * 32;

    {
        const uint4* srcH = (const uint4*)g_eBh;
        uint4* dstH = (uint4*)(smem + OFF_BH);
        for (int idx = t; idx < BT_HALF/16; idx += 256)
            dstH[idx] = srcH[idx];
    }
    if (t < 128) { b2s[t] = e2b[t]; eiws[t] = eiw[t]; }
    {
        __half2 dh  = __float2half2_rn(g_D2 [bi * NPTS + t]);
        __half2 d0h = __float2half2_rn(g_D02[bi * NPTS + t]);
        d2h[t]  = *reinterpret_cast<uint32_t*>(&dh);
        d02h[t] = *reinterpret_cast<uint32_t*>(&d0h);
    }

    const int k0 = lane * 4;
    float4 pabf = *reinterpret_cast<const float4*>(&g_PA[bi * HD + k0]);
    const float4 b1_4 = *reinterpret_cast<const float4*>(&e1b[k0]);
    const float4 w256f = *reinterpret_cast<const float4*>(&e1w[256 * HD + k0]);
    const float4 w257f = *reinterpret_cast<const float4*>(&e1w[257 * HD + k0]);
    const __half2 pab01 = __floats2half2_rn(pabf.x + b1_4.x, pabf.y + b1_4.y);
    const __half2 pab23 = __floats2half2_rn(pabf.z + b1_4.z, pabf.w + b1_4.w);
    const __half2 w256_01 = __floats2half2_rn(w256f.x, w256f.y);
    const __half2 w256_23 = __floats2half2_rn(w256f.z, w256f.w);
    const __half2 w257_01 = __floats2half2_rn(w257f.x, w257f.y);
    const __half2 w257_23 = __floats2half2_rn(w257f.z, w257f.w);
    const float bi0 = eib[0];
    const __half* PBb = g_PBh + (size_t)b * NPTS * HD;

    float aggacc[8];
    #pragma unroll
    for (int c = 0; c < 8; c++) aggacc[c] = 0.f;

    __syncthreads();
    produce_tile_h2(w, lane, 0, pab01, pab23, w256_01, w256_23,
                    w257_01, w257_23, PBb, d2h, d02h, smem32);
    __syncthreads();

    for (int tile = 0; tile < 8; tile++) {
        const int j0 = tile * JT;
        const uint32_t aBuf = smem32 + (tile & 1) * ABUF_BYTES;
        if (tile < 7)
            produce_tile_h2(w, lane, j0 + JT, pab01, pab23, w256_01, w256_23,
                            w257_01, w257_23, PBb, d2h, d02h,
                            smem32 + ((tile + 1) & 1) * ABUF_BYTES);

        float acc[4][4];
        #pragma unroll
        for (int a = 0; a < 4; a++)
            #pragma unroll
            for (int e = 0; e < 4; e++) acc[a][e] = 0.f;
        gemm_warp(acc, mrow0, ncol0, lane, aBuf, bH32);

        // m = silu(D + b2); per-row dots with eiw
        float dot0 = 0.f, dot1 = 0.f;
        #pragma unroll
        for (int ni = 0; ni < 4; ni++) {
            int c0 = ncol0 + ni * 8 + 2 * s;
            float b2a = b2s[c0], b2b = b2s[c0 + 1];
            float* A = acc[ni];
            A[0] = silu_fast(A[0] + b2a); A[1] = silu_fast(A[1] + b2b);
            A[2] = silu_fast(A[2] + b2a); A[3] = silu_fast(A[3] + b2b);
            float ea = eiws[c0], eb = eiws[c0 + 1];
            dot0 += A[0]*ea + A[1]*eb;
            dot1 += A[2]*ea + A[3]*eb;
        }
        dot0 += __shfl_xor_sync(0xffffffffu, dot0, 1);
        dot0 += __shfl_xor_sync(0xffffffffu, dot0, 2);
        dot1 += __shfl_xor_sync(0xffffffffu, dot1, 1);
        dot1 += __shfl_xor_sync(0xffffffffu, dot1, 2);
        if (s == 0) {
            dotP[(w >> 1) * JT + mrow0 + q]     = dot0;
            dotP[(w >> 1) * JT + mrow0 + q + 8] = dot1;
        }
        __syncthreads();
        if (t < JT) {
            float sv = dotP[t] + dotP[JT + t] + dotP[2*JT + t]
                     + dotP[3*JT + t] + bi0;
            float e = sigm(sv);
            if (j0 + t == i) e = 0.f;
            e_s[t] = e;
        }
        __syncthreads();
        {
            float e0 = e_s[mrow0 + q], e1 = e_s[mrow0 + q + 8];
            #pragma unroll
            for (int ni = 0; ni < 4; ni++) {
                float* A = acc[ni];
                aggacc[ni*2+0] = fmaf(e0, A[0], fmaf(e1, A[2], aggacc[ni*2+0]));
                aggacc[ni*2+1] = fmaf(e0, A[1], fmaf(e1, A[3], aggacc[ni*2+1]));
            }
        }
    }
    // reduce aggacc over q-lanes (cols depend only on s)
    #pragma unroll
    for (int c = 0; c < 8; c++) {
        float v = aggacc[c];
        v += __shfl_xor_sync(0xffffffffu, v, 4);
        v += __shfl_xor_sync(0xffffffffu, v, 8);
        v += __shfl_xor_sync(0xffffffffu, v, 16);
        aggacc[c] = v;
    }
    __syncthreads();
    if (q == 0) {
        #pragma unroll
        for (int ni = 0; ni < 4; ni++) {
            aggW[w * 32 + ni * 8 + 2 * s]     = aggacc[ni*2+0];
            aggW[w * 32 + ni * 8 + 2 * s + 1] = aggacc[ni*2+1];
        }
    }
    __syncthreads();
    if (t < 128) {
        int cq = t >> 5, cl = t & 31;
        float sv = aggW[(2*cq) * 32 + cl] + aggW[(2*cq + 1) * 32 + cl];
        g_agg[bi * HD + t] = sv * (1.0f / 256.0f);
    }
}

// ---------------- kernel 4: coordinate chain -> g_upd ----------------------
// ext words: d2h[256] d02h[256] | floats: d2all[256] b2s[128] c3ws[128]
//            dotP[128] updx/y/z[96]
__global__ void __launch_bounds__(256, 3) cor_kernel(
    const float* __restrict__ c1w, const float* __restrict__ c1b,
    const float* __restrict__ c2b,
    const float* __restrict__ c3w, const float* __restrict__ c3b,
    const float* __restrict__ x)
{
    extern __shared__ __align__(16) unsigned char smem[];
    uint32_t* extw = (uint32_t*)(smem + OFF_EXT);
    uint32_t* d2h   = extw;        uint32_t* d02h = extw + 256;
    float* ext    = (float*)(extw + 512);
    float* d2all  = ext;         float* b2s = ext + 256;
    float* c3ws   = ext + 384;
    float* dotP   = ext + 512;   // 4*32
    float* updx   = ext + 640;   float* updy = ext + 672;  float* updz = ext + 704;

    const uint32_t smem32 = smem_u32(smem);
    const uint32_t bH32 = smem32 + OFF_BH;

    const int bi = blockIdx.x;
    const int b  = bi >> 8;
    const int i  = bi & 255;
    const int t  = threadIdx.x;
    const int lane = t & 31, w = t >> 5;
    const int s = lane & 3, q = lane >> 2;
    const int mrow0 = (w & 1) * 16, ncol0 = (w >> 1) * 32;

    {
        const uint4* srcH = (const uint4*)g_cBh;
        uint4* dstH = (uint4*)(smem + OFF_BH);
        for (int idx = t; idx < BT_HALF/16; idx += 256)
            dstH[idx] = srcH[idx];
    }
    if (t < 128) { b2s[t] = c2b[t]; c3ws[t] = c3w[t]; }
    {
        float dv  = g_D2 [bi * NPTS + t];
        float d0v = g_D02[bi * NPTS + t];
        d2all[t] = dv;
        __half2 dh  = __float2half2_rn(dv);
        __half2 d0h = __float2half2_rn(d0v);
        d2h[t]  = *reinterpret_cast<uint32_t*>(&dh);
        d02h[t] = *reinterpret_cast<uint32_t*>(&d0h);
    }

    const int k0 = lane * 4;
    float4 pabf = *reinterpret_cast<const float4*>(&g_CA[bi * HD + k0]);
    const float4 b1_4 = *reinterpret_cast<const float4*>(&c1b[k0]);
    const float4 w256f = *reinterpret_cast<const float4*>(&c1w[256 * HD + k0]);
    const float4 w257f = *reinterpret_cast<const float4*>(&c1w[257 * HD + k0]);
    const __half2 pab01 = __floats2half2_rn(pabf.x + b1_4.x, pabf.y + b1_4.y);
    const __half2 pab23 = __floats2half2_rn(pabf.z + b1_4.z, pabf.w + b1_4.w);
    const __half2 w256_01 = __floats2half2_rn(w256f.x, w256f.y);
    const __half2 w256_23 = __floats2half2_rn(w256f.z, w256f.w);
    const __half2 w257_01 = __floats2half2_rn(w257f.x, w257f.y);
    const __half2 w257_23 = __floats2half2_rn(w257f.z, w257f.w);
    const float b3 = c3b[0];
    const __half* CBb = g_CBh + (size_t)b * NPTS * HD;

    const float xi0 = x[bi * 3 + 0];
    const float xi1 = x[bi * 3 + 1];
    const float xi2 = x[bi * 3 + 2];
    float ux = 0.f, uy = 0.f, uz = 0.f;

    __syncthreads();
    produce_tile_h2(w, lane, 0, pab01, pab23, w256_01, w256_23,
                    w257_01, w257_23, CBb, d2h, d02h, smem32);
    __syncthreads();

    for (int tile = 0; tile < 8; tile++) {
        const int j0 = tile * JT;
        const uint32_t aBuf = smem32 + (tile & 1) * ABUF_BYTES;
        if (tile < 7)
            produce_tile_h2(w, lane, j0 + JT, pab01, pab23, w256_01, w256_23,
                            w257_01, w257_23, CBb, d2h, d02h,
                            smem32 + ((tile + 1) & 1) * ABUF_BYTES);

        float acc[4][4];
        #pragma unroll
        for (int a = 0; a < 4; a++)
            #pragma unroll
            for (int e = 0; e < 4; e++) acc[a][e] = 0.f;
        gemm_warp(acc, mrow0, ncol0, lane, aBuf, bH32);

        float dot0 = 0.f, dot1 = 0.f;
        #pragma unroll
        for (int ni = 0; ni < 4; ni++) {
            int c0 = ncol0 + ni * 8 + 2 * s;
            float b2a = b2s[c0], b2b = b2s[c0 + 1];
            float* A = acc[ni];
            float m0 = silu_fast(A[0] + b2a), m1 = silu_fast(A[1] + b2b);
            float m2 = silu_fast(A[2] + b2a), m3 = silu_fast(A[3] + b2b);
            float wa = c3ws[c0], wb = c3ws[c0 + 1];
            dot0 += m0*wa + m1*wb;
            dot1 += m2*wa + m3*wb;
        }
        dot0 += __shfl_xor_sync(0xffffffffu, dot0, 1);
        dot0 += __shfl_xor_sync(0xffffffffu, dot0, 2);
        dot1 += __shfl_xor_sync(0xffffffffu, dot1, 1);
        dot1 += __shfl_xor_sync(0xffffffffu, dot1, 2);
        if (s == 0) {
            dotP[(w >> 1) * JT + mrow0 + q]     = dot0;
            dotP[(w >> 1) * JT + mrow0 + q + 8] = dot1;
        }
        __syncthreads();
        if (t < JT) {
            int j = j0 + t;
            if (j != i) {
                float cw = dotP[t] + dotP[JT + t] + dotP[2*JT + t]
                         + dotP[3*JT + t] + b3;
                float d2v = d2all[j];
                float dist = (d2v > 0.f) ? sqrtf(d2v) : 0.f;
                float f = __fdividef(cw, dist + 1.f);
                const float* xj = x + ((size_t)b * NPTS + j) * 3;
                ux = fmaf(f, xi0 - xj[0], ux);
                uy = fmaf(f, xi1 - xj[1], uy);
                uz = fmaf(f, xi2 - xj[2], uz);
            }
        }
        __syncthreads();   // protect dotP from next iter's writes
    }
    if (t < JT) { updx[t] = ux; updy[t] = uy; updz[t] = uz; }
    __syncthreads();
    if (t < 3) {
        const float* arr = (t == 0) ? updx : (t == 1) ? updy : updz;
        float sv = 0.f;
        for (int r = 0; r < JT; r++) sv += arr[r];
        g_upd[bi * 3 + t] = sv * (1.0f / 256.0f);
    }
}

// ---------------- kernel 5: node MLP + outputs -----------------------------
__global__ void __launch_bounds__(128) final_kernel(
    const float* __restrict__ hin, const float* __restrict__ xin,
    const float* __restrict__ pm,
    const float* __restrict__ n1w, const float* __restrict__ n1b,
    const float* __restrict__ n2w, const float* __restrict__ n2b,
    float* __restrict__ out)
{
    const int r0 = blockIdx.x * 8;
    const int t  = threadIdx.x;
    __shared__ float nin[8][256];
    __shared__ float tmid[8][HD];
    #pragma unroll
    for (int r = 0; r < 8; r++) {
        nin[r][t]       = hin[(r0 + r) * HD + t];
        nin[r][HD + t]  = g_agg[(r0 + r) * HD + t];
    }
    __syncthreads();
    float a[8];
    #pragma unroll
    for (int r = 0; r < 8; r++) a[r] = n1b[t];
    for (int k = 0; k < 256; k++) {
        float wv = n1w[k * HD + t];
        #pragma unroll
        for (int r = 0; r < 8; r++) a[r] = fmaf(nin[r][k], wv, a[r]);
    }
    #pragma unroll
    for (int r = 0; r < 8; r++) tmid[r][t] = siluf(a[r]);
    __syncthreads();
    #pragma unroll
    for (int r = 0; r < 8; r++) a[r] = n2b[t];
    for (int k = 0; k < HD; k++) {
        float wv = n2w[k * HD + t];
        #pragma unroll
        for (int r = 0; r < 8; r++) a[r] = fmaf(tmid[r][k], wv, a[r]);
    }
    float* outx = out;                  // x_next: BN*3
    float* outh = out + BN * 3;         // h_next: BN*HD
    #pragma unroll
    for (int r = 0; r < 8; r++) {
        int bi = r0 + r;
        float mask = pm[bi];
        outh[bi * HD + t] = (nin[r][t] + a[r]) * mask;
        if (t < 3) outx[bi * 3 + t] = (xin[bi * 3 + t] + g_upd[bi * 3 + t]) * mask;
    }
}

// ---------------- launch ----------------------------------------------------
extern "C" void kernel_launch(void* const* d_in, const int* in_sizes, int n_in,
                              void* d_out, int out_size)
{
    const float* x   = (const float*)d_in[0];
    const float* h   = (const float*)d_in[1];
    const float* x0  = (const float*)d_in[2];
    const float* pm  = (const float*)d_in[3];
    const float* e1w = (const float*)d_in[4];
    const float* e1b = (const float*)d_in[5];
    const float* e2w = (const float*)d_in[6];
    const float* e2b = (const float*)d_in[7];
    const float* eiw = (const float*)d_in[8];
    const float* eib = (const float*)d_in[9];
    const float* n1w = (const float*)d_in[10];
    const float* n1b = (const float*)d_in[11];
    const float* n2w = (const float*)d_in[12];
    const float* n2b = (const float*)d_in[13];
    const float* c1w = (const float*)d_in[14];
    const float* c1b = (const float*)d_in[15];
    const float* c2w = (const float*)d_in[16];
    const float* c2b = (const float*)d_in[17];
    const float* c3w = (const float*)d_in[18];
    const float* c3b = (const float*)d_in[19];
    float* out = (float*)d_out;

    cudaFuncSetAttribute(edge_kernel,
        cudaFuncAttributeMaxDynamicSharedMemorySize, E_SMEM_TOTAL);
    cudaFuncSetAttribute(cor_kernel,
        cudaFuncAttributeMaxDynamicSharedMemorySize, C_SMEM_TOTAL);

    prep_kernel<<<128, 128>>>(e2w, c2w);
    proj_kernel<<<BN / 8, 128>>>(h, e1w, c1w);
    dist_kernel<<<(BN * NPTS) / 256, 256>>>(x, x0);
    edge_kernel<<<BN, 256, E_SMEM_TOTAL>>>(e1w, e1b, e2b, eiw, eib);
    cor_kernel<<<BN, 256, C_SMEM_TOTAL>>>(c1w, c1b, c2b, c3w, c3b, x);
    final_kernel<<<BN / 8, 128>>>(h, x, pm, n1w, n1b, n2w, n2b, out);
}

// round 17
// speedup vs baseline: 1.5351x; 1.1846x over previous
#include <cuda_runtime.h>
#include <cuda_fp16.h>
#include <math.h>
#include <stdint.h>

// Problem constants
#define BATCH 8
#define NPTS 256
#define HD 128
#define BN (BATCH*NPTS)          // 2048 rows
#define BSTRIDE 136              // padded row stride (fp16 elems) for ldmatrix
#define ROWB (BSTRIDE*2)         // 272 bytes per row
#define JT 64                    // j-tile rows
#define NTILES (NPTS/JT)         // 4
#define BT_HALF (128*ROWB)       // 34816 : B tile (fp16)
#define ABUF_BYTES (JT*ROWB)     // 17408 per A buffer

// ---------------- scratch (device globals; no allocation allowed) ----------
__device__ float g_PA[BN*HD];
__device__ float g_CA[BN*HD];
__device__ __align__(16) __half g_PBh[BN*HD];   // fp16 PB (producer operand)
__device__ __align__(16) __half g_CBh[BN*HD];   // fp16 CB
__device__ float g_D2[BN*NPTS];
__device__ float g_D02[BN*NPTS];
__device__ float g_agg[BN*HD];
__device__ float g_upd[BN*3];
// W2^T in padded [n][k] fp16 layout (prep_kernel fills)
__device__ __align__(16) __half g_eBh[128*BSTRIDE];
__device__ __align__(16) __half g_cBh[128*BSTRIDE];

// precise sigmoid (gates only)
__device__ __forceinline__ float sigm(float v) {
    return __fdividef(1.f, 1.f + __expf(-v));
}
__device__ __forceinline__ float siluf(float v) {
    return v * sigm(v);
}
// fast silu fp32: 1 MUFU (tanh.approx)
__device__ __forceinline__ float silu_fast(float v) {
    float h = 0.5f * v;
    float t;
    asm("tanh.approx.f32 %0, %1;" : "=f"(t) : "f"(h));
    return fmaf(h, t, h);
}
// packed half2 silu
__device__ __forceinline__ __half2 silu_h2(__half2 v) {
    __half2 h = __hmul2(v, __float2half2_rn(0.5f));
    uint32_t hu = *reinterpret_cast<uint32_t*>(&h);
    uint32_t tu;
    asm("tanh.approx.f16x2 %0, %1;" : "=r"(tu) : "r"(hu));
    __half2 t = *reinterpret_cast<__half2*>(&tu);
    return __hfma2(h, t, h);
}

__device__ __forceinline__ uint32_t smem_u32(const void* p) {
    uint32_t a;
    asm("{ .reg .u64 tmp; cvta.to.shared.u64 tmp, %1; cvt.u32.u64 %0, tmp; }"
        : "=r"(a) : "l"(p));
    return a;
}

__device__ __forceinline__ void ldsm4(uint32_t r[4], uint32_t addr) {
    asm volatile("ldmatrix.sync.aligned.m8n8.x4.shared.b16 {%0,%1,%2,%3}, [%4];"
        : "=r"(r[0]), "=r"(r[1]), "=r"(r[2]), "=r"(r[3]) : "r"(addr));
}

__device__ __forceinline__ void mma_f16(float d[4], const uint32_t a[4],
                                        const uint32_t b0, const uint32_t b1) {
    asm volatile(
        "mma.sync.aligned.m16n8k16.row.col.f32.f16.f16.f32 "
        "{%0,%1,%2,%3}, {%4,%5,%6,%7}, {%8,%9}, {%0,%1,%2,%3};"
        : "+f"(d[0]), "+f"(d[1]), "+f"(d[2]), "+f"(d[3])
        : "r"(a[0]), "r"(a[1]), "r"(a[2]), "r"(a[3]), "r"(b0), "r"(b1));
}

// ---------------- kernel 0: prep W2^T fp16 padded tiles --------------------
__global__ void __launch_bounds__(128) prep_kernel(
    const float* __restrict__ e2w, const float* __restrict__ c2w)
{
    int n = blockIdx.x;
    int k = threadIdx.x;
    int idx = n * BSTRIDE + k;
    g_eBh[idx] = __float2half_rn(e2w[k * HD + n]);
    g_cBh[idx] = __float2half_rn(c2w[k * HD + n]);
}

// ---------------- kernel 1: per-node projections ---------------------------
__global__ void __launch_bounds__(128) proj_kernel(
    const float* __restrict__ h,
    const float* __restrict__ e1w,
    const float* __restrict__ c1w)
{
    const int r0 = blockIdx.x * 8;
    const int t  = threadIdx.x;
    __shared__ float hs[8][HD];
    #pragma unroll
    for (int r = 0; r < 8; r++) hs[r][t] = h[(r0 + r) * HD + t];
    __syncthreads();

    float pa[8], pb[8], ca[8], cb[8];
    #pragma unroll
    for (int r = 0; r < 8; r++) { pa[r]=0.f; pb[r]=0.f; ca[r]=0.f; cb[r]=0.f; }

    for (int k = 0; k < HD; k++) {
        float wea = e1w[k * HD + t];
        float web = e1w[(HD + k) * HD + t];
        float wca = c1w[k * HD + t];
        float wcb = c1w[(HD + k) * HD + t];
        #pragma unroll
        for (int r = 0; r < 8; r++) {
            float hk = hs[r][k];
            pa[r] = fmaf(hk, wea, pa[r]);
            pb[r] = fmaf(hk, web, pb[r]);
            ca[r] = fmaf(hk, wca, ca[r]);
            cb[r] = fmaf(hk, wcb, cb[r]);
        }
    }
    #pragma unroll
    for (int r = 0; r < 8; r++) {
        int bi = r0 + r;
        g_PA[bi * HD + t]  = pa[r];
        g_CA[bi * HD + t]  = ca[r];
        g_PBh[bi * HD + t] = __float2half_rn(pb[r]);
        g_CBh[bi * HD + t] = __float2half_rn(cb[r]);
    }
}

// ---------------- kernel 2: pairwise squared distances ---------------------
__global__ void __launch_bounds__(256) dist_kernel(
    const float* __restrict__ x, const float* __restrict__ x0)
{
    int idx = blockIdx.x * 256 + threadIdx.x;
    int j = idx & 255;
    int bi = idx >> 8;
    int b  = bi >> 8;
    const float* xi = x  + bi * 3;
    const float* xj = x  + (b * NPTS + j) * 3;
    float dx = xi[0]-xj[0], dy = xi[1]-xj[1], dz = xi[2]-xj[2];
    g_D2[idx] = dx*dx + dy*dy + dz*dz;
    const float* yi = x0 + bi * 3;
    const float* yj = x0 + (b * NPTS + j) * 3;
    float ex = yi[0]-yj[0], ey = yi[1]-yj[1], ez = yi[2]-yj[2];
    g_D02[idx] = ex*ex + ey*ey + ez*ez;
}

// ============================================================================
// smem layout (bytes):
//   [0      : 17408)   A buffer 0 (64 x 136 fp16)
//   [17408  : 34816)   A buffer 1
//   [34816  : 69632)   B tile (128 x 136 fp16)
//   [69632  : ...)     ext scratch (32-bit words)
// ============================================================================
#define OFF_BH   34816
#define OFF_EXT  69632
#define E_SMEM_TOTAL (OFF_EXT + 1344*4)
#define C_SMEM_TOTAL (OFF_EXT + 1472*4)

// half2 producer: warp w -> local rows w*8..w*8+7; lane -> k = lane*4..+3.
__device__ __forceinline__ void produce_tile_h2(
    int w, int lane, int j0,
    __half2 pab01, __half2 pab23,
    __half2 w256_01, __half2 w256_23, __half2 w257_01, __half2 w257_23,
    const __half* __restrict__ Pbh,
    const uint32_t* d2h, const uint32_t* d02h,
    uint32_t aBuf)
{
    const int k0 = lane * 4;
    #pragma unroll
    for (int rr = 0; rr < 8; rr++) {
        int row = w * 8 + rr;
        const uint2 pb = *reinterpret_cast<const uint2*>(
            &Pbh[(size_t)(j0 + row) * HD + k0]);
        __half2 pb01 = *reinterpret_cast<const __half2*>(&pb.x);
        __half2 pb23 = *reinterpret_cast<const __half2*>(&pb.y);
        uint32_t dju = d2h[j0 + row], d0ju = d02h[j0 + row];
        __half2 dj  = *reinterpret_cast<__half2*>(&dju);
        __half2 d0j = *reinterpret_cast<__half2*>(&d0ju);
        __half2 v01 = __hadd2(pab01, pb01);
        v01 = __hfma2(dj, w256_01, v01);
        v01 = __hfma2(d0j, w257_01, v01);
        __half2 v23 = __hadd2(pab23, pb23);
        v23 = __hfma2(dj, w256_23, v23);
        v23 = __hfma2(d0j, w257_23, v23);
        v01 = silu_h2(v01);
        v23 = silu_h2(v23);
        uint32_t off = row * ROWB + lane * 8;
        asm volatile("st.shared.v2.b32 [%0], {%1, %2};"
            :: "r"(aBuf + off),
               "r"(*reinterpret_cast<uint32_t*>(&v01)),
               "r"(*reinterpret_cast<uint32_t*>(&v23)) : "memory");
    }
}

// warp GEMM: 32m x 32n warp tile; acc[mi][ni][4], mi: 16-row frag, ni: 8-col.
__device__ __forceinline__ void gemm_warp32(
    float acc[2][4][4], int mrow0, int ncol0, int lane,
    uint32_t aBuf, uint32_t bH32)
{
    uint32_t aoff[2], boff[2];
    {
        int arow = (lane & 15);
        int akp  = (lane >> 4) * 8;
        #pragma unroll
        for (int mi = 0; mi < 2; mi++)
            aoff[mi] = (mrow0 + mi * 16 + arow) * ROWB + akp * 2;
        int bn = (lane & 7) + ((lane >> 4) & 1) * 8;
        int bkp = ((lane >> 3) & 1) * 8;
        #pragma unroll
        for (int nb = 0; nb < 2; nb++)
            boff[nb] = (ncol0 + nb * 16 + bn) * ROWB + bkp * 2;
    }
    #pragma unroll
    for (int ks = 0; ks < 8; ks++) {
        const uint32_t kb = ks * 32;
        uint32_t ah[2][4], bh[2][4];
        #pragma unroll
        for (int mi = 0; mi < 2; mi++)
            ldsm4(ah[mi], aBuf + aoff[mi] + kb);
        #pragma unroll
        for (int nb = 0; nb < 2; nb++)
            ldsm4(bh[nb], bH32 + boff[nb] + kb);
        #pragma unroll
        for (int mi = 0; mi < 2; mi++)
            #pragma unroll
            for (int nb = 0; nb < 2; nb++) {
                mma_f16(acc[mi][2*nb],     ah[mi], bh[nb][0], bh[nb][1]);
                mma_f16(acc[mi][2*nb + 1], ah[mi], bh[nb][2], bh[nb][3]);
            }
    }
}

// ---------------- kernel 3: edge chain -> g_agg ----------------------------
// ext words: d2h[256] d02h[256] | floats: b2s[128] eiws[128] dotP[256]
//            e_s[64] aggW[256]
__global__ void __launch_bounds__(256, 3) edge_kernel(
    const float* __restrict__ e1w, const float* __restrict__ e1b,
    const float* __restrict__ e2b,
    const float* __restrict__ eiw, const float* __restrict__ eib)
{
    extern __shared__ __align__(16) unsigned char smem[];
    uint32_t* extw = (uint32_t*)(smem + OFF_EXT);
    uint32_t* d2h   = extw;        uint32_t* d02h = extw + 256;
    float* ext    = (float*)(extw + 512);
    float* b2s    = ext;         float* eiws   = ext + 128;
    float* dotP   = ext + 256;   // 4 ngroups x 64 rows
    float* e_s    = ext + 512;   // 64
    float* aggW   = ext + 576;   // 8*32

    const uint32_t smem32 = smem_u32(smem);
    const uint32_t bH32 = smem32 + OFF_BH;

    const int bi = blockIdx.x;
    const int b  = bi >> 8;
    const int i  = bi & 255;
    const int t  = threadIdx.x;
    const int lane = t & 31, w = t >> 5;
    const int s = lane & 3, q = lane >> 2;
    const int mrow0 = (w & 1) * 32, ncol0 = (w >> 1) * 32;

    {
        const uint4* srcH = (const uint4*)g_eBh;
        uint4* dstH = (uint4*)(smem + OFF_BH);
        for (int idx = t; idx < BT_HALF/16; idx += 256)
            dstH[idx] = srcH[idx];
    }
    if (t < 128) { b2s[t] = e2b[t]; eiws[t] = eiw[t]; }
    {
        __half2 dh  = __float2half2_rn(g_D2 [bi * NPTS + t]);
        __half2 d0h = __float2half2_rn(g_D02[bi * NPTS + t]);
        d2h[t]  = *reinterpret_cast<uint32_t*>(&dh);
        d02h[t] = *reinterpret_cast<uint32_t*>(&d0h);
    }

    const int k0 = lane * 4;
    float4 pabf = *reinterpret_cast<const float4*>(&g_PA[bi * HD + k0]);
    const float4 b1_4 = *reinterpret_cast<const float4*>(&e1b[k0]);
    const float4 w256f = *reinterpret_cast<const float4*>(&e1w[256 * HD + k0]);
    const float4 w257f = *reinterpret_cast<const float4*>(&e1w[257 * HD + k0]);
    const __half2 pab01 = __floats2half2_rn(pabf.x + b1_4.x, pabf.y + b1_4.y);
    const __half2 pab23 = __floats2half2_rn(pabf.z + b1_4.z, pabf.w + b1_4.w);
    const __half2 w256_01 = __floats2half2_rn(w256f.x, w256f.y);
    const __half2 w256_23 = __floats2half2_rn(w256f.z, w256f.w);
    const __half2 w257_01 = __floats2half2_rn(w257f.x, w257f.y);
    const __half2 w257_23 = __floats2half2_rn(w257f.z, w257f.w);
    const float bi0 = eib[0];
    const __half* PBb = g_PBh + (size_t)b * NPTS * HD;

    float aggacc[8];
    #pragma unroll
    for (int c = 0; c < 8; c++) aggacc[c] = 0.f;

    __syncthreads();
    produce_tile_h2(w, lane, 0, pab01, pab23, w256_01, w256_23,
                    w257_01, w257_23, PBb, d2h, d02h, smem32);
    __syncthreads();

    for (int tile = 0; tile < NTILES; tile++) {
        const int j0 = tile * JT;
        const uint32_t aBuf = smem32 + (tile & 1) * ABUF_BYTES;
        if (tile < NTILES - 1)
            produce_tile_h2(w, lane, j0 + JT, pab01, pab23, w256_01, w256_23,
                            w257_01, w257_23, PBb, d2h, d02h,
                            smem32 + ((tile + 1) & 1) * ABUF_BYTES);

        float acc[2][4][4];
        #pragma unroll
        for (int mi = 0; mi < 2; mi++)
            #pragma unroll
            for (int a = 0; a < 4; a++)
                #pragma unroll
                for (int e = 0; e < 4; e++) acc[mi][a][e] = 0.f;
        gemm_warp32(acc, mrow0, ncol0, lane, aBuf, bH32);

        // m = silu(D + b2); per-row dots with eiw (4 rows per thread)
        float dotR[4] = {0.f, 0.f, 0.f, 0.f};
        #pragma unroll
        for (int mi = 0; mi < 2; mi++)
            #pragma unroll
            for (int ni = 0; ni < 4; ni++) {
                int c0 = ncol0 + ni * 8 + 2 * s;
                float b2a = b2s[c0], b2b = b2s[c0 + 1];
                float* A = acc[mi][ni];
                A[0] = silu_fast(A[0] + b2a); A[1] = silu_fast(A[1] + b2b);
                A[2] = silu_fast(A[2] + b2a); A[3] = silu_fast(A[3] + b2b);
                float ea = eiws[c0], eb = eiws[c0 + 1];
                dotR[mi*2+0] += A[0]*ea + A[1]*eb;
                dotR[mi*2+1] += A[2]*ea + A[3]*eb;
            }
        #pragma unroll
        for (int r = 0; r < 4; r++) {
            dotR[r] += __shfl_xor_sync(0xffffffffu, dotR[r], 1);
            dotR[r] += __shfl_xor_sync(0xffffffffu, dotR[r], 2);
        }
        if (s == 0) {
            float* dp = dotP + (w >> 1) * JT;
            dp[mrow0 + q]      = dotR[0];
            dp[mrow0 + q + 8]  = dotR[1];
            dp[mrow0 + 16 + q]     = dotR[2];
            dp[mrow0 + 16 + q + 8] = dotR[3];
        }
        __syncthreads();
        if (t < JT) {
            float sv = dotP[t] + dotP[JT + t] + dotP[2*JT + t]
                     + dotP[3*JT + t] + bi0;
            float e = sigm(sv);
            if (j0 + t == i) e = 0.f;
            e_s[t] = e;
        }
        __syncthreads();
        #pragma unroll
        for (int mi = 0; mi < 2; mi++) {
            float e0 = e_s[mrow0 + mi*16 + q], e1 = e_s[mrow0 + mi*16 + q + 8];
            #pragma unroll
            for (int ni = 0; ni < 4; ni++) {
                float* A = acc[mi][ni];
                aggacc[ni*2+0] = fmaf(e0, A[0], fmaf(e1, A[2], aggacc[ni*2+0]));
                aggacc[ni*2+1] = fmaf(e0, A[1], fmaf(e1, A[3], aggacc[ni*2+1]));
            }
        }
    }
    // reduce aggacc over q-lanes (cols depend only on s)
    #pragma unroll
    for (int c = 0; c < 8; c++) {
        float v = aggacc[c];
        v += __shfl_xor_sync(0xffffffffu, v, 4);
        v += __shfl_xor_sync(0xffffffffu, v, 8);
        v += __shfl_xor_sync(0xffffffffu, v, 16);
        aggacc[c] = v;
    }
    __syncthreads();
    if (q == 0) {
        #pragma unroll
        for (int ni = 0; ni < 4; ni++) {
            aggW[w * 32 + ni * 8 + 2 * s]     = aggacc[ni*2+0];
            aggW[w * 32 + ni * 8 + 2 * s + 1] = aggacc[ni*2+1];
        }
    }
    __syncthreads();
    if (t < 128) {
        int cq = t >> 5, cl = t & 31;
        float sv = aggW[(2*cq) * 32 + cl] + aggW[(2*cq + 1) * 32 + cl];
        g_agg[bi * HD + t] = sv * (1.0f / 256.0f);
    }
}

// ---------------- kernel 4: coordinate chain -> g_upd ----------------------
// ext words: d2h[256] d02h[256] | floats: d2all[256] b2s[128] c3ws[128]
//            dotP[256] updx/y/z[192]
__global__ void __launch_bounds__(256, 3) cor_kernel(
    const float* __restrict__ c1w, const float* __restrict__ c1b,
    const float* __restrict__ c2b,
    const float* __restrict__ c3w, const float* __restrict__ c3b,
    const float* __restrict__ x)
{
    extern __shared__ __align__(16) unsigned char smem[];
    uint32_t* extw = (uint32_t*)(smem + OFF_EXT);
    uint32_t* d2h   = extw;        uint32_t* d02h = extw + 256;
    float* ext    = (float*)(extw + 512);
    float* d2all  = ext;         float* b2s = ext + 256;
    float* c3ws   = ext + 384;
    float* dotP   = ext + 512;   // 4 x 64
    float* updx   = ext + 768;   float* updy = ext + 832;  float* updz = ext + 896;

    const uint32_t smem32 = smem_u32(smem);
    const uint32_t bH32 = smem32 + OFF_BH;

    const int bi = blockIdx.x;
    const int b  = bi >> 8;
    const int i  = bi & 255;
    const int t  = threadIdx.x;
    const int lane = t & 31, w = t >> 5;
    const int s = lane & 3, q = lane >> 2;
    const int mrow0 = (w & 1) * 32, ncol0 = (w >> 1) * 32;

    {
        const uint4* srcH = (const uint4*)g_cBh;
        uint4* dstH = (uint4*)(smem + OFF_BH);
        for (int idx = t; idx < BT_HALF/16; idx += 256)
            dstH[idx] = srcH[idx];
    }
    if (t < 128) { b2s[t] = c2b[t]; c3ws[t] = c3w[t]; }
    {
        float dv  = g_D2 [bi * NPTS + t];
        float d0v = g_D02[bi * NPTS + t];
        d2all[t] = dv;
        __half2 dh  = __float2half2_rn(dv);
        __half2 d0h = __float2half2_rn(d0v);
        d2h[t]  = *reinterpret_cast<uint32_t*>(&dh);
        d02h[t] = *reinterpret_cast<uint32_t*>(&d0h);
    }

    const int k0 = lane * 4;
    float4 pabf = *reinterpret_cast<const float4*>(&g_CA[bi * HD + k0]);
    const float4 b1_4 = *reinterpret_cast<const float4*>(&c1b[k0]);
    const float4 w256f = *reinterpret_cast<const float4*>(&c1w[256 * HD + k0]);
    const float4 w257f = *reinterpret_cast<const float4*>(&c1w[257 * HD + k0]);
    const __half2 pab01 = __floats2half2_rn(pabf.x + b1_4.x, pabf.y + b1_4.y);
    const __half2 pab23 = __floats2half2_rn(pabf.z + b1_4.z, pabf.w + b1_4.w);
    const __half2 w256_01 = __floats2half2_rn(w256f.x, w256f.y);
    const __half2 w256_23 = __floats2half2_rn(w256f.z, w256f.w);
    const __half2 w257_01 = __floats2half2_rn(w257f.x, w257f.y);
    const __half2 w257_23 = __floats2half2_rn(w257f.z, w257f.w);
    const float b3 = c3b[0];
    const __half* CBb = g_CBh + (size_t)b * NPTS * HD;

    const float xi0 = x[bi * 3 + 0];
    const float xi1 = x[bi * 3 + 1];
    const float xi2 = x[bi * 3 + 2];
    float ux = 0.f, uy = 0.f, uz = 0.f;

    __syncthreads();
    produce_tile_h2(w, lane, 0, pab01, pab23, w256_01, w256_23,
                    w257_01, w257_23, CBb, d2h, d02h, smem32);
    __syncthreads();

    for (int tile = 0; tile < NTILES; tile++) {
        const int j0 = tile * JT;
        const uint32_t aBuf = smem32 + (tile & 1) * ABUF_BYTES;
        if (tile < NTILES - 1)
            produce_tile_h2(w, lane, j0 + JT, pab01, pab23, w256_01, w256_23,
                            w257_01, w257_23, CBb, d2h, d02h,
                            smem32 + ((tile + 1) & 1) * ABUF_BYTES);

        float acc[2][4][4];
        #pragma unroll
        for (int mi = 0; mi < 2; mi++)
            #pragma unroll
            for (int a = 0; a < 4; a++)
                #pragma unroll
                for (int e = 0; e < 4; e++) acc[mi][a][e] = 0.f;
        gemm_warp32(acc, mrow0, ncol0, lane, aBuf, bH32);

        float dotR[4] = {0.f, 0.f, 0.f, 0.f};
        #pragma unroll
        for (int mi = 0; mi < 2; mi++)
            #pragma unroll
            for (int ni = 0; ni < 4; ni++) {
                int c0 = ncol0 + ni * 8 + 2 * s;
                float b2a = b2s[c0], b2b = b2s[c0 + 1];
                float* A = acc[mi][ni];
                float m0 = silu_fast(A[0] + b2a), m1 = silu_fast(A[1] + b2b);
                float m2 = silu_fast(A[2] + b2a), m3 = silu_fast(A[3] + b2b);
                float wa = c3ws[c0], wb = c3ws[c0 + 1];
                dotR[mi*2+0] += m0*wa + m1*wb;
                dotR[mi*2+1] += m2*wa + m3*wb;
            }
        #pragma unroll
        for (int r = 0; r < 4; r++) {
            dotR[r] += __shfl_xor_sync(0xffffffffu, dotR[r], 1);
            dotR[r] += __shfl_xor_sync(0xffffffffu, dotR[r], 2);
        }
        if (s == 0) {
            float* dp = dotP + (w >> 1) * JT;
            dp[mrow0 + q]      = dotR[0];
            dp[mrow0 + q + 8]  = dotR[1];
            dp[mrow0 + 16 + q]     = dotR[2];
            dp[mrow0 + 16 + q + 8] = dotR[3];
        }
        __syncthreads();
        if (t < JT) {
            int j = j0 + t;
            if (j != i) {
                float cw = dotP[t] + dotP[JT + t] + dotP[2*JT + t]
                         + dotP[3*JT + t] + b3;
                float d2v = d2all[j];
                float dist = (d2v > 0.f) ? sqrtf(d2v) : 0.f;
                float f = __fdividef(cw, dist + 1.f);
                const float* xj = x + ((size_t)b * NPTS + j) * 3;
                ux = fmaf(f, xi0 - xj[0], ux);
                uy = fmaf(f, xi1 - xj[1], uy);
                uz = fmaf(f, xi2 - xj[2], uz);
            }
        }
        __syncthreads();   // protect dotP from next iter's writes
    }
    if (t < JT) { updx[t] = ux; updy[t] = uy; updz[t] = uz; }
    __syncthreads();
    if (t < 3) {
        const float* arr = (t == 0) ? updx : (t == 1) ? updy : updz;
        float sv = 0.f;
        for (int r = 0; r < JT; r++) sv += arr[r];
        g_upd[bi * 3 + t] = sv * (1.0f / 256.0f);
    }
}

// ---------------- kernel 5: node MLP + outputs -----------------------------
__global__ void __launch_bounds__(128) final_kernel(
    const float* __restrict__ hin, const float* __restrict__ xin,
    const float* __restrict__ pm,
    const float* __restrict__ n1w, const float* __restrict__ n1b,
    const float* __restrict__ n2w, const float* __restrict__ n2b,
    float* __restrict__ out)
{
    const int r0 = blockIdx.x * 8;
    const int t  = threadIdx.x;
    __shared__ float nin[8][256];
    __shared__ float tmid[8][HD];
    #pragma unroll
    for (int r = 0; r < 8; r++) {
        nin[r][t]       = hin[(r0 + r) * HD + t];
        nin[r][HD + t]  = g_agg[(r0 + r) * HD + t];
    }
    __syncthreads();
    float a[8];
    #pragma unroll
    for (int r = 0; r < 8; r++) a[r] = n1b[t];
    for (int k = 0; k < 256; k++) {
        float wv = n1w[k * HD + t];
        #pragma unroll
        for (int r = 0; r < 8; r++) a[r] = fmaf(nin[r][k], wv, a[r]);
    }
    #pragma unroll
    for (int r = 0; r < 8; r++) tmid[r][t] = siluf(a[r]);
    __syncthreads();
    #pragma unroll
    for (int r = 0; r < 8; r++) a[r] = n2b[t];
    for (int k = 0; k < HD; k++) {
        float wv = n2w[k * HD + t];
        #pragma unroll
        for (int r = 0; r < 8; r++) a[r] = fmaf(tmid[r][k], wv, a[r]);
    }
    float* outx = out;                  // x_next: BN*3
    float* outh = out + BN * 3;         // h_next: BN*HD
    #pragma unroll
    for (int r = 0; r < 8; r++) {
        int bi = r0 + r;
        float mask = pm[bi];
        outh[bi * HD + t] = (nin[r][t] + a[r]) * mask;
        if (t < 3) outx[bi * 3 + t] = (xin[bi * 3 + t] + g_upd[bi * 3 + t]) * mask;
    }
}

// ---------------- launch ----------------------------------------------------
extern "C" void kernel_launch(void* const* d_in, const int* in_sizes, int n_in,
                              void* d_out, int out_size)
{
    const float* x   = (const float*)d_in[0];
    const float* h   = (const float*)d_in[1];
    const float* x0  = (const float*)d_in[2];
    const float* pm  = (const float*)d_in[3];
    const float* e1w = (const float*)d_in[4];
    const float* e1b = (const float*)d_in[5];
    const float* e2w = (const float*)d_in[6];
    const float* e2b = (const float*)d_in[7];
    const float* eiw = (const float*)d_in[8];
    const float* eib = (const float*)d_in[9];
    const float* n1w = (const float*)d_in[10];
    const float* n1b = (const float*)d_in[11];
    const float* n2w = (const float*)d_in[12];
    const float* n2b = (const float*)d_in[13];
    const float* c1w = (const float*)d_in[14];
    const float* c1b = (const float*)d_in[15];
    const float* c2w = (const float*)d_in[16];
    const float* c2b = (const float*)d_in[17];
    const float* c3w = (const float*)d_in[18];
    const float* c3b = (const float*)d_in[19];
    float* out = (float*)d_out;

    cudaFuncSetAttribute(edge_kernel,
        cudaFuncAttributeMaxDynamicSharedMemorySize, E_SMEM_TOTAL);
    cudaFuncSetAttribute(cor_kernel,
        cudaFuncAttributeMaxDynamicSharedMemorySize, C_SMEM_TOTAL);

    prep_kernel<<<128, 128>>>(e2w, c2w);
    proj_kernel<<<BN / 8, 128>>>(h, e1w, c1w);
    dist_kernel<<<(BN * NPTS) / 256, 256>>>(x, x0);
    edge_kernel<<<BN, 256, E_SMEM_TOTAL>>>(e1w, e1b, e2b, eiw, eib);
    cor_kernel<<<BN, 256, C_SMEM_TOTAL>>>(c1w, c1b, c2b, c3w, c3b, x);
    final_kernel<<<BN / 8, 128>>>(h, x, pm, n1w, n1b, n2w, n2b, out);
}